// round 8
// baseline (speedup 1.0000x reference)
#include <cuda_runtime.h>
#include <cstdint>

// ---------------------------------------------------------------------------
// MultiMolNet: per-atom typed 3-layer MLP + masked per-molecule sum.
// Identity: sum over all 8 type-MLPs = f_{type}(feats) + (C - Z_type),
// Z_t = f_t(0), C = sum_t Z_t  ->  one MLP eval per atom.
//
// R8: layer-1 on mma.sync.m16n8k8 TF32 (base-target PTX; tcgen05 is an 'a'
//     feature the harness target rejects). 3-term hi/lo split for fp32-grade
//     accuracy. Fragments pre-arranged in smem; cp.async staged. Layers 2/3
//     stay on the FP32 pipe.
// ---------------------------------------------------------------------------

namespace {
constexpr int B_  = 4096;
constexpr int A_  = 64;
constexpr int F_  = 124;
constexpr int T_  = 8;
constexpr int H1_ = 64;
constexpr int H2_ = 16;
constexpr int NATOM = B_ * A_;     // 262144
constexpr int ROW   = F_ + 1;      // 125
constexpr int BM    = 128;         // atoms per tile (= MMA M)
constexpr int MLP_BLOCKS = NATOM / BM + T_;   // 2056

// --- smem layout (float indices) ---
// raw staging (double buffered): rawA [128][33], rawB [32][64]
constexpr int RAW_A0 = 0;        // 4224
constexpr int RAW_B0 = 4224;     // 2048
constexpr int RAW_A1 = 6272;     // 4224
constexpr int RAW_B1 = 10496;    // 2048  -> raw region ends at 12544
// fragment-ordered tiles (persistent across chunks):
// A_FRAG: 16 ks x 8 warp-blocks x 32 lanes x float4 (raw fp32)   = 16384 fl
// B_FRAG: 16 ks x 8 n-tiles    x 32 lanes x float4 (hi0,hi1,lo0,lo1) = 16384 fl
constexpr int A_FRAG = 12544;
constexpr int B_FRAG = 28928;
// epilogue h1s[128][68] overlays raw region [0..8704)
constexpr int U_H1S = 0;
// small params
constexpr int S_W2   = 45312;    // 1024 (16B aligned)
constexpr int S_B1   = 46336;    // 64
constexpr int S_B2   = 46400;    // 16
constexpr int S_W3   = 46416;    // 16
constexpr int S_MISC = 46432;    // [0]=corr, [1]=b3
constexpr int S_IDX  = 46436;    // 128 ints
constexpr int SMEM_FLOATS = 46564;
constexpr int SMEM_BYTES  = SMEM_FLOATS * 4;   // ~182 KB -> 1 CTA/SM
}

// ---- scratch ----
__device__ int   g_counts[T_];
__device__ int   g_bucket[T_ * NATOM];
__device__ float g_corr[T_];
__device__ float g_atom[NATOM];

// ---- helpers ----
__device__ __forceinline__ uint32_t smem_u32(const void* p) {
    return (uint32_t)__cvta_generic_to_shared(p);
}
__device__ __forceinline__ float tf32_hi(float x) {
    uint32_t u;
    asm("cvt.rna.tf32.f32 %0, %1;" : "=r"(u) : "f"(x));
    return __uint_as_float(u);
}
__device__ __forceinline__ void cp_async4(uint32_t dst, const void* src) {
    asm volatile("cp.async.ca.shared.global [%0], [%1], 4;"
                 :: "r"(dst), "l"(src) : "memory");
}
__device__ __forceinline__ void cp_async16(uint32_t dst, const void* src) {
    asm volatile("cp.async.cg.shared.global [%0], [%1], 16;"
                 :: "r"(dst), "l"(src) : "memory");
}
#define CP_COMMIT() asm volatile("cp.async.commit_group;" ::: "memory")
#define CP_WAIT(n)  asm volatile("cp.async.wait_group %0;" :: "n"(n) : "memory")

// m16n8k8 tf32 MMA: D(f32) += A(tf32) * B(tf32). Row-major A, col-major B.
__device__ __forceinline__ void mma_tf32(float d[4], const uint32_t a[4],
                                         uint32_t b0, uint32_t b1) {
    asm volatile(
        "mma.sync.aligned.m16n8k8.row.col.f32.tf32.tf32.f32 "
        "{%0,%1,%2,%3}, {%4,%5,%6,%7}, {%8,%9}, {%0,%1,%2,%3};"
        : "+f"(d[0]), "+f"(d[1]), "+f"(d[2]), "+f"(d[3])
        : "r"(a[0]), "r"(a[1]), "r"(a[2]), "r"(a[3]), "r"(b0), "r"(b1));
}

// ---- f32x2 packed FMA (kept for layer 2) ----
__device__ __forceinline__ void ffma2(unsigned long long& d,
                                      unsigned long long a, unsigned long long b) {
    asm("fma.rn.f32x2 %0, %1, %2, %3;" : "=l"(d) : "l"(a), "l"(b), "l"(d));
}
__device__ __forceinline__ unsigned long long pack2(float lo, float hi) {
    unsigned long long r;
    asm("mov.b64 %0, {%1, %2};" : "=l"(r) : "f"(lo), "f"(hi));
    return r;
}
__device__ __forceinline__ void unpack2(unsigned long long v, float& lo, float& hi) {
    asm("mov.b64 {%0, %1}, %2;" : "=f"(lo), "=f"(hi) : "l"(v));
}

// ===========================================================================
__global__ void k_init(const float* __restrict__ b1, const float* __restrict__ W2,
                       const float* __restrict__ b2, const float* __restrict__ W3,
                       const float* __restrict__ b3) {
    __shared__ float zs[T_];
    int t = threadIdx.x;
    if (t < T_) {
        g_counts[t] = 0;
        float h1z[H1_];
        #pragma unroll
        for (int h = 0; h < H1_; h++) h1z[h] = fmaxf(b1[t * H1_ + h], 0.0f);
        float o = b3[t];
        for (int g = 0; g < H2_; g++) {
            float s = b2[t * H2_ + g];
            #pragma unroll
            for (int k = 0; k < H1_; k++)
                s += h1z[k] * W2[t * H1_ * H2_ + k * H2_ + g];
            o += fmaxf(s, 0.0f) * W3[t * H2_ + g];
        }
        zs[t] = o;
    }
    __syncthreads();
    if (t < T_) {
        float C = 0.0f;
        #pragma unroll
        for (int tt = 0; tt < T_; tt++) C += zs[tt];
        g_corr[t] = C - zs[t];
    }
}

__global__ void k_bucket(const float* __restrict__ x) {
    __shared__ int scnt[T_], sbase[T_];
    int tid = threadIdx.x;
    if (tid < T_) scnt[tid] = 0;
    __syncthreads();
    int i = blockIdx.x * 256 + tid;
    int t = (int)x[(long long)i * ROW];
    int r = atomicAdd(&scnt[t], 1);
    __syncthreads();
    if (tid < T_) sbase[tid] = atomicAdd(&g_counts[tid], scnt[tid]);
    __syncthreads();
    g_bucket[t * NATOM + sbase[t] + r] = i;
}

// ===========================================================================
// K2: layer-1 via mma.sync tf32 (3-term split), layers 2/3 on FP32 pipe.
//   warp w owns atom rows [16w, 16w+16); all 64 N-cols via 8 n-tiles.
// ===========================================================================
__global__ void __launch_bounds__(256, 1)
k_mlp(const float* __restrict__ x,  const float* __restrict__ mask,
      const float* __restrict__ W1, const float* __restrict__ b1,
      const float* __restrict__ W2, const float* __restrict__ b2,
      const float* __restrict__ W3, const float* __restrict__ b3) {
    extern __shared__ float sm[];
    int* s_idx = (int*)&sm[S_IDX];
    const int tid  = threadIdx.x;
    const int warp = tid >> 5;
    const int lane = tid & 31;

    // ---- map block -> (type, tile) ----
    int t = -1, tile = 0, cnt = 0;
    {
        int rem = blockIdx.x;
        #pragma unroll
        for (int tt = 0; tt < T_; tt++) {
            int c  = g_counts[tt];
            int nt = (c + BM - 1) >> 7;
            if (t < 0) {
                if (rem < nt) { t = tt; tile = rem; cnt = c; }
                else rem -= nt;
            }
        }
    }
    if (t < 0) return;

    const uint32_t smb = smem_u32(sm);

    // ---- prologue: params + atom indices ----
    for (int i = tid; i < H1_ * H2_; i += 256)
        sm[S_W2 + i] = W2[t * H1_ * H2_ + i];
    if (tid < H1_) sm[S_B1 + tid] = b1[t * H1_ + tid];
    if (tid < H2_) sm[S_B2 + tid] = b2[t * H2_ + tid];
    if (tid < H2_) sm[S_W3 + tid] = W3[t * H2_ + tid];
    if (tid == 0) { sm[S_MISC] = g_corr[t]; sm[S_MISC + 1] = b3[t]; }
    if (tid < BM) {
        int gi = tile * BM + tid;
        s_idx[tid] = (gi < cnt) ? g_bucket[t * NATOM + gi] : -1;
    }
    __syncthreads();                          // s_idx visible to all warps

    const int RAW_A[2] = {RAW_A0, RAW_A1};
    const int RAW_B[2] = {RAW_B0, RAW_B1};
    const float* w1_t = W1 + t * F_ * H1_;

    // ---- raw-chunk issue (cp.async) ----
    auto issue_raw = [&](int c, int rb) {
        const int kb = c * 32;
        const int kl = (c == 3) ? 28 : 32;
        // feats: warp w fills atom slots [16w,16w+16), lane = k-within-chunk
        const uint32_t ra = smb + RAW_A[rb] * 4;
        const int slot0 = warp * 16;
        #pragma unroll
        for (int a = 0; a < 16; a++) {
            int sid = s_idx[slot0 + a];
            if (sid >= 0 && lane < kl) {
                const float* src = x + (long long)sid * ROW + 1 + kb + lane;
                cp_async4(ra + (uint32_t)((slot0 + a) * 33 + lane) * 4u, src);
            }
        }
        // W1 chunk rows [kb, kb+kl): contiguous, 16B units
        const uint32_t rbu = smb + RAW_B[rb] * 4;
        const char* wsrc = (const char*)(w1_t + kb * H1_);
        const int units = kl * 16;            // kl * 64 * 4 / 16
        for (int u = tid; u < units; u += 256)
            cp_async16(rbu + (uint32_t)u * 16u, wsrc + (size_t)u * 16u);
    };

    // ---- reorder raw -> fragment-ordered tiles (A raw fp32, B hi/lo) ----
    // m16n8k8 frag maps: A a0=(r=l>>2, k=l&3) a1=(r+8,k) a2=(r,k+4) a3=(r+8,k+4)
    //                    B b0=(k=l&3, n=l>>2) b1=(k+4, n)
    auto split_chunk = [&](int c, int rb) {
        const int kl = (c == 3) ? 28 : 32;    // valid local k in this chunk
        const float* rawA = &sm[RAW_A[rb]];
        const float* rawB = &sm[RAW_B[rb]];
        #pragma unroll
        for (int q = 0; q < 4; q++) {         // A: 1024 float4 slots / chunk
            int s = tid + q * 256;
            int l = s & 31, wr = (s >> 5) & 7, ksl = s >> 8;
            int r0 = wr * 16 + (l >> 2);
            int k0 = ksl * 8 + (l & 3);
            float a0 = (k0 < kl)     ? rawA[r0 * 33 + k0]           : 0.0f;
            float a1 = (k0 < kl)     ? rawA[(r0 + 8) * 33 + k0]     : 0.0f;
            float a2 = (k0 + 4 < kl) ? rawA[r0 * 33 + k0 + 4]       : 0.0f;
            float a3 = (k0 + 4 < kl) ? rawA[(r0 + 8) * 33 + k0 + 4] : 0.0f;
            int ks = c * 4 + ksl;
            *(float4*)&sm[A_FRAG + ((ks * 8 + wr) * 32 + l) * 4] =
                make_float4(a0, a1, a2, a3);
        }
        #pragma unroll
        for (int q = 0; q < 4; q++) {         // B: 1024 float4 slots / chunk
            int s = tid + q * 256;
            int l = s & 31, nt = (s >> 5) & 7, ksl = s >> 8;
            int n  = nt * 8 + (l >> 2);
            int k0 = ksl * 8 + (l & 3);
            float v0 = (k0 < kl)     ? rawB[k0 * H1_ + n]       : 0.0f;
            float v1 = (k0 + 4 < kl) ? rawB[(k0 + 4) * H1_ + n] : 0.0f;
            float h0 = tf32_hi(v0), h1v = tf32_hi(v1);
            int ks = c * 4 + ksl;
            *(float4*)&sm[B_FRAG + ((ks * 8 + nt) * 32 + l) * 4] =
                make_float4(h0, h1v, v0 - h0, v1 - h1v);
        }
    };

    // ---- staging pipeline over 4 K-chunks {32,32,32,28} ----
    issue_raw(0, 0); CP_COMMIT();
    issue_raw(1, 1); CP_COMMIT();
    CP_WAIT(1); __syncthreads();              // raw0 resident
    split_chunk(0, 0);
    __syncthreads();                          // raw0 free
    issue_raw(2, 0); CP_COMMIT();
    CP_WAIT(1); __syncthreads();              // raw1 resident
    split_chunk(1, 1);
    __syncthreads();                          // raw1 free
    issue_raw(3, 1); CP_COMMIT();
    CP_WAIT(1); __syncthreads();              // raw2 resident
    split_chunk(2, 0);
    CP_WAIT(0); __syncthreads();              // raw3 resident
    split_chunk(3, 1);
    __syncthreads();                          // all fragments written

    // ---- layer-1 mainloop: 16 ks x 8 nt x 3 MMA, all operands LDS.128 ----
    float acc[8][4];
    #pragma unroll
    for (int nt = 0; nt < 8; nt++)
        #pragma unroll
        for (int j = 0; j < 4; j++) acc[nt][j] = 0.0f;

    #pragma unroll 1
    for (int ks = 0; ks < 16; ks++) {
        float4 av = *(const float4*)&sm[A_FRAG + ((ks * 8 + warp) * 32 + lane) * 4];
        uint32_t Ahi[4], Alo[4];
        {
            float a[4] = {av.x, av.y, av.z, av.w};
            #pragma unroll
            for (int j = 0; j < 4; j++) {
                float h = tf32_hi(a[j]);
                Ahi[j] = __float_as_uint(h);
                Alo[j] = __float_as_uint(a[j] - h);
            }
        }
        #pragma unroll
        for (int nt = 0; nt < 8; nt++) {
            float4 bv = *(const float4*)&sm[B_FRAG + ((ks * 8 + nt) * 32 + lane) * 4];
            uint32_t bh0 = __float_as_uint(bv.x), bh1 = __float_as_uint(bv.y);
            uint32_t bl0 = __float_as_uint(bv.z), bl1 = __float_as_uint(bv.w);
            mma_tf32(acc[nt], Ahi, bh0, bh1);   // Ah*Bh
            mma_tf32(acc[nt], Ahi, bl0, bl1);   // Ah*Bl
            mma_tf32(acc[nt], Alo, bh0, bh1);   // Al*Bh
        }
    }

    // ---- layer-1 epilogue: bias + relu -> h1s[atom][68] (overlays raw) ----
    // D frag: c0=(r=l>>2, col=2*(l&3)) c1=(r, col+1) c2=(r+8, col) c3=(r+8, col+1)
    {
        const int r = warp * 16 + (lane >> 2);
        #pragma unroll
        for (int nt = 0; nt < 8; nt++) {
            int cb = nt * 8 + 2 * (lane & 3);
            float ba = sm[S_B1 + cb], bb = sm[S_B1 + cb + 1];
            float2 v0 = make_float2(fmaxf(acc[nt][0] + ba, 0.0f),
                                    fmaxf(acc[nt][1] + bb, 0.0f));
            float2 v1 = make_float2(fmaxf(acc[nt][2] + ba, 0.0f),
                                    fmaxf(acc[nt][3] + bb, 0.0f));
            *(float2*)&sm[U_H1S + r * 68 + cb]       = v0;
            *(float2*)&sm[U_H1S + (r + 8) * 68 + cb] = v1;
        }
    }
    __syncthreads();

    // ---- layers 2+3 fused (tid < 128, one atom each) ----
    if (tid < BM) {
        float h1r[H1_];
        #pragma unroll
        for (int q = 0; q < 16; q++)
            *(float4*)&h1r[q * 4] = *(const float4*)&sm[U_H1S + tid * 68 + q * 4];

        unsigned long long accg[8];
        #pragma unroll
        for (int gp = 0; gp < 8; gp++)
            accg[gp] = *(const unsigned long long*)&sm[S_B2 + gp * 2];

        const ulonglong2* w2v = (const ulonglong2*)&sm[S_W2];
        #pragma unroll 8
        for (int k = 0; k < H1_; k++) {
            unsigned long long hkk = pack2(h1r[k], h1r[k]);
            #pragma unroll
            for (int gq = 0; gq < 4; gq++) {
                ulonglong2 w = w2v[k * 4 + gq];
                ffma2(accg[gq * 2],     hkk, w.x);
                ffma2(accg[gq * 2 + 1], hkk, w.y);
            }
        }

        float o = sm[S_MISC + 1];
        #pragma unroll
        for (int gp = 0; gp < 8; gp++) {
            float lo, hi; unpack2(accg[gp], lo, hi);
            o += fmaxf(lo, 0.0f) * sm[S_W3 + gp * 2]
               + fmaxf(hi, 0.0f) * sm[S_W3 + gp * 2 + 1];
        }
        int idx = s_idx[tid];
        if (idx >= 0)
            g_atom[idx] = (o + sm[S_MISC]) * mask[idx];
    }
}

// ===========================================================================
__global__ void k_reduce(float* __restrict__ out) {
    int warp = threadIdx.x >> 5, lane = threadIdx.x & 31;
    int m = blockIdx.x * 8 + warp;
    const float* p = g_atom + m * A_;
    float s = p[lane] + p[lane + 32];
    #pragma unroll
    for (int o = 16; o > 0; o >>= 1) s += __shfl_xor_sync(0xffffffffu, s, o);
    if (lane == 0) out[m] = s;
}

// ===========================================================================
extern "C" void kernel_launch(void* const* d_in, const int* in_sizes, int n_in,
                              void* d_out, int out_size) {
    const float* x    = (const float*)d_in[0];
    const float* mask = (const float*)d_in[1];
    const float* W1   = (const float*)d_in[2];
    const float* b1   = (const float*)d_in[3];
    const float* W2   = (const float*)d_in[4];
    const float* b2   = (const float*)d_in[5];
    const float* W3   = (const float*)d_in[6];
    const float* b3   = (const float*)d_in[7];

    cudaFuncSetAttribute(k_mlp, cudaFuncAttributeMaxDynamicSharedMemorySize,
                         SMEM_BYTES);

    k_init<<<1, 32>>>(b1, W2, b2, W3, b3);
    k_bucket<<<NATOM / 256, 256>>>(x);
    k_mlp<<<MLP_BLOCKS, 256, SMEM_BYTES>>>(x, mask, W1, b1, W2, b2, W3, b3);
    k_reduce<<<B_ / 8, 256>>>((float*)d_out);
}

// round 9
// speedup vs baseline: 1.3080x; 1.3080x over previous
#include <cuda_runtime.h>
#include <cstdint>

// ---------------------------------------------------------------------------
// MultiMolNet: per-atom typed 3-layer MLP + masked per-molecule sum.
// Identity: sum over all 8 type-MLPs = f_{type}(feats) + (C - Z_type),
// Z_t = f_t(0), C = sum_t Z_t  ->  one MLP eval per atom.
//
// R9: layer-1 on mma.sync.m16n8k8 TF32, 3-term hi/lo split.
//  - B (W1) fragments precomputed ONCE per type into gmem (k_binit);
//    mainloop streams them via coalesced LDG.128 (L1/L2 resident).
//  - A gather lands DIRECTLY in fragment order via cp.async scatter
//    (no raw buffer, no reorder pass, one wait).
//  - 69 KB smem -> 2 CTAs/SM; 4 barriers total.
// ---------------------------------------------------------------------------

namespace {
constexpr int B_  = 4096;
constexpr int A_  = 64;
constexpr int F_  = 124;
constexpr int T_  = 8;
constexpr int H1_ = 64;
constexpr int H2_ = 16;
constexpr int NATOM = B_ * A_;     // 262144
constexpr int ROW   = F_ + 1;      // 125
constexpr int BM    = 128;         // atoms per tile (= MMA M)
constexpr int MLP_BLOCKS = NATOM / BM + T_;   // 2056
constexpr int NKS   = 16;          // k-steps of 8 (124 padded to 128)

// --- smem layout (float indices) ---
// A_FRAG: 16 ks x 8 warp-blocks x 32 lanes x float4 = 16384 floats (64 KB)
// h1s[128][68] overlays A_FRAG after layer-1 (barrier-protected)
constexpr int A_FRAG = 0;
constexpr int U_H1S  = 0;
constexpr int S_W2   = 16384;    // 1024 (byte 65536, 16B aligned)
constexpr int S_B1   = S_W2 + 1024;
constexpr int S_B2   = S_B1 + 64;
constexpr int S_W3   = S_B2 + 16;
constexpr int S_MISC = S_W3 + 16;   // [0]=corr, [1]=b3
constexpr int S_IDX  = S_MISC + 4;  // 128 ints
constexpr int SMEM_FLOATS = S_IDX + BM;
constexpr int SMEM_BYTES  = SMEM_FLOATS * 4;   // 70544 B -> 2 CTAs/SM
}

// ---- scratch ----
__device__ int    g_counts[T_];
__device__ int    g_bucket[T_ * NATOM];
__device__ float  g_corr[T_];
__device__ float  g_atom[NATOM];
// B fragments per type: 16 ks x 8 nt x 32 lanes x (h0,h1,l0,l1)
__device__ float4 g_bfrag[T_ * NKS * 8 * 32];   // 512 KB

// ---- helpers ----
__device__ __forceinline__ uint32_t smem_u32(const void* p) {
    return (uint32_t)__cvta_generic_to_shared(p);
}
__device__ __forceinline__ float tf32_hi(float x) {
    uint32_t u;
    asm("cvt.rna.tf32.f32 %0, %1;" : "=r"(u) : "f"(x));
    return __uint_as_float(u);
}
__device__ __forceinline__ void cp_async4(uint32_t dst, const void* src) {
    asm volatile("cp.async.ca.shared.global [%0], [%1], 4;"
                 :: "r"(dst), "l"(src) : "memory");
}
#define CP_COMMIT() asm volatile("cp.async.commit_group;" ::: "memory")
#define CP_WAIT(n)  asm volatile("cp.async.wait_group %0;" :: "n"(n) : "memory")

// m16n8k8 tf32 MMA: D(f32) += A(tf32) * B(tf32). Row-major A, col-major B.
__device__ __forceinline__ void mma_tf32(float d[4], const uint32_t a[4],
                                         uint32_t b0, uint32_t b1) {
    asm volatile(
        "mma.sync.aligned.m16n8k8.row.col.f32.tf32.tf32.f32 "
        "{%0,%1,%2,%3}, {%4,%5,%6,%7}, {%8,%9}, {%0,%1,%2,%3};"
        : "+f"(d[0]), "+f"(d[1]), "+f"(d[2]), "+f"(d[3])
        : "r"(a[0]), "r"(a[1]), "r"(a[2]), "r"(a[3]), "r"(b0), "r"(b1));
}

// ---- f32x2 packed FMA (layer 2) ----
__device__ __forceinline__ void ffma2(unsigned long long& d,
                                      unsigned long long a, unsigned long long b) {
    asm("fma.rn.f32x2 %0, %1, %2, %3;" : "=l"(d) : "l"(a), "l"(b), "l"(d));
}
__device__ __forceinline__ unsigned long long pack2(float lo, float hi) {
    unsigned long long r;
    asm("mov.b64 %0, {%1, %2};" : "=l"(r) : "f"(lo), "f"(hi));
    return r;
}
__device__ __forceinline__ void unpack2(unsigned long long v, float& lo, float& hi) {
    asm("mov.b64 {%0, %1}, %2;" : "=f"(lo), "=f"(hi) : "l"(v));
}

// ===========================================================================
// K0: Z_t = f_t(0), corr_t = C - Z_t; zero counters.
// ===========================================================================
__global__ void k_init(const float* __restrict__ b1, const float* __restrict__ W2,
                       const float* __restrict__ b2, const float* __restrict__ W3,
                       const float* __restrict__ b3) {
    __shared__ float zs[T_];
    int t = threadIdx.x;
    if (t < T_) {
        g_counts[t] = 0;
        float h1z[H1_];
        #pragma unroll
        for (int h = 0; h < H1_; h++) h1z[h] = fmaxf(b1[t * H1_ + h], 0.0f);
        float o = b3[t];
        for (int g = 0; g < H2_; g++) {
            float s = b2[t * H2_ + g];
            #pragma unroll
            for (int k = 0; k < H1_; k++)
                s += h1z[k] * W2[t * H1_ * H2_ + k * H2_ + g];
            o += fmaxf(s, 0.0f) * W3[t * H2_ + g];
        }
        zs[t] = o;
    }
    __syncthreads();
    if (t < T_) {
        float C = 0.0f;
        #pragma unroll
        for (int tt = 0; tt < T_; tt++) C += zs[tt];
        g_corr[t] = C - zs[t];
    }
}

// ===========================================================================
// K0b: precompute B (W1) hi/lo fragments per type. 8 blocks x 256 threads.
// frag map (m16n8k8 B, col-major): b0=(k=l&3, n=l>>2), b1=(k+4, n)
// ===========================================================================
__global__ void k_binit(const float* __restrict__ W1) {
    int t = blockIdx.x;
    const float* w = W1 + t * F_ * H1_;
    for (int s = threadIdx.x; s < NKS * 8 * 32; s += 256) {
        int l = s & 31, nt = (s >> 5) & 7, ks = s >> 8;
        int n  = nt * 8 + (l >> 2);
        int k0 = ks * 8 + (l & 3);
        float v0 = (k0 < F_)     ? w[k0 * H1_ + n]       : 0.0f;
        float v1 = (k0 + 4 < F_) ? w[(k0 + 4) * H1_ + n] : 0.0f;
        float h0 = tf32_hi(v0), h1 = tf32_hi(v1);
        g_bfrag[t * (NKS * 8 * 32) + s] = make_float4(h0, h1, v0 - h0, v1 - h1);
    }
}

// ===========================================================================
// K1: bucket atom indices by type (order nondeterminism harmless).
// ===========================================================================
__global__ void k_bucket(const float* __restrict__ x) {
    __shared__ int scnt[T_], sbase[T_];
    int tid = threadIdx.x;
    if (tid < T_) scnt[tid] = 0;
    __syncthreads();
    int i = blockIdx.x * 256 + tid;
    int t = (int)x[(long long)i * ROW];
    int r = atomicAdd(&scnt[t], 1);
    __syncthreads();
    if (tid < T_) sbase[tid] = atomicAdd(&g_counts[tid], scnt[tid]);
    __syncthreads();
    g_bucket[t * NATOM + sbase[t] + r] = i;
}

// ===========================================================================
// K2: layer-1 via mma.sync tf32 (A frags in smem, B frags via LDG),
//     layers 2/3 on FP32 pipe. Warp w owns atom rows [16w, 16w+16).
// A frag map (m16n8k8): a0=(r=l>>2,k=l&3) a1=(r+8,k) a2=(r,k+4) a3=(r+8,k+4)
// ===========================================================================
__global__ void __launch_bounds__(256, 2)
k_mlp(const float* __restrict__ x,  const float* __restrict__ mask,
      const float* __restrict__ W1, const float* __restrict__ b1,
      const float* __restrict__ W2, const float* __restrict__ b2,
      const float* __restrict__ W3, const float* __restrict__ b3) {
    extern __shared__ float sm[];
    int* s_idx = (int*)&sm[S_IDX];
    const int tid  = threadIdx.x;
    const int warp = tid >> 5;
    const int lane = tid & 31;

    // ---- map block -> (type, tile) ----
    int t = -1, tile = 0, cnt = 0;
    {
        int rem = blockIdx.x;
        #pragma unroll
        for (int tt = 0; tt < T_; tt++) {
            int c  = g_counts[tt];
            int nt = (c + BM - 1) >> 7;
            if (t < 0) {
                if (rem < nt) { t = tt; tile = rem; cnt = c; }
                else rem -= nt;
            }
        }
    }
    if (t < 0) return;

    const uint32_t smb = smem_u32(sm);

    // ---- prologue: params, atom indices, zero A_FRAG ----
    for (int i = tid; i < H1_ * H2_; i += 256)
        sm[S_W2 + i] = W2[t * H1_ * H2_ + i];
    if (tid < H1_) sm[S_B1 + tid] = b1[t * H1_ + tid];
    if (tid < H2_) sm[S_B2 + tid] = b2[t * H2_ + tid];
    if (tid < H2_) sm[S_W3 + tid] = W3[t * H2_ + tid];
    if (tid == 0) { sm[S_MISC] = g_corr[t]; sm[S_MISC + 1] = b3[t]; }
    if (tid < BM) {
        int gi = tile * BM + tid;
        s_idx[tid] = (gi < cnt) ? g_bucket[t * NATOM + gi] : -1;
    }
    {
        float4 z4 = make_float4(0.f, 0.f, 0.f, 0.f);
        #pragma unroll
        for (int q = 0; q < 16; q++)
            *(float4*)&sm[A_FRAG + (tid + q * 256) * 4] = z4;
    }
    __syncthreads();   // zeros + s_idx visible before cp.async writes

    // ---- A gather: cp.async scatter directly into fragment order ----
    // warp w loads atom slots [16w,16w+16); lane = k within 32-chunk.
    {
        const int slot0 = warp * 16;
        #pragma unroll 4
        for (int a = 0; a < 16; a++) {
            int sid = s_idx[slot0 + a];
            if (sid < 0) continue;
            const float* srcrow = x + (long long)sid * ROW + 1;
            const int regbase  = (a >= 8) ? 1 : 0;        // rr>=8 -> a1/a3
            const int lanebase = (a & 7) * 4;
            #pragma unroll
            for (int c = 0; c < 4; c++) {
                int k = c * 32 + lane;
                if (k < F_) {
                    int ks = k >> 3, kk = k & 7;
                    int reg = regbase + ((kk >= 4) ? 2 : 0);
                    int dl  = lanebase + (kk & 3);
                    uint32_t dst = smb + (uint32_t)(
                        (A_FRAG + ((ks * 8 + warp) * 32 + dl) * 4 + reg) * 4);
                    cp_async4(dst, srcrow + k);
                }
            }
        }
    }
    CP_COMMIT();
    CP_WAIT(0);
    __syncthreads();   // all A fragments resident

    // ---- layer-1 mainloop: 16 ks x 8 nt x 3 MMA ----
    float acc[8][4];
    #pragma unroll
    for (int nt = 0; nt < 8; nt++)
        #pragma unroll
        for (int j = 0; j < 4; j++) acc[nt][j] = 0.0f;

    const float4* __restrict__ bfr = g_bfrag + t * (NKS * 8 * 32);
    #pragma unroll 1
    for (int ks = 0; ks < NKS; ks++) {
        float4 av = *(const float4*)&sm[A_FRAG + ((ks * 8 + warp) * 32 + lane) * 4];
        uint32_t Ahi[4], Alo[4];
        {
            float a[4] = {av.x, av.y, av.z, av.w};
            #pragma unroll
            for (int j = 0; j < 4; j++) {
                float h = tf32_hi(a[j]);
                Ahi[j] = __float_as_uint(h);
                Alo[j] = __float_as_uint(a[j] - h);
            }
        }
        #pragma unroll
        for (int nt = 0; nt < 8; nt++) {
            float4 bv = __ldg(&bfr[(ks * 8 + nt) * 32 + lane]);
            uint32_t bh0 = __float_as_uint(bv.x), bh1 = __float_as_uint(bv.y);
            uint32_t bl0 = __float_as_uint(bv.z), bl1 = __float_as_uint(bv.w);
            mma_tf32(acc[nt], Ahi, bh0, bh1);   // Ah*Bh
            mma_tf32(acc[nt], Ahi, bl0, bl1);   // Ah*Bl
            mma_tf32(acc[nt], Alo, bh0, bh1);   // Al*Bh
        }
    }
    __syncthreads();   // all warps done reading A_FRAG before h1s overlay

    // ---- layer-1 epilogue: bias + relu -> h1s[atom][68] ----
    // D frag: c0=(r=l>>2, col=2*(l&3)) c1=(r,col+1) c2=(r+8,col) c3=(r+8,col+1)
    {
        const int r = warp * 16 + (lane >> 2);
        #pragma unroll
        for (int nt = 0; nt < 8; nt++) {
            int cb = nt * 8 + 2 * (lane & 3);
            float ba = sm[S_B1 + cb], bb = sm[S_B1 + cb + 1];
            float2 v0 = make_float2(fmaxf(acc[nt][0] + ba, 0.0f),
                                    fmaxf(acc[nt][1] + bb, 0.0f));
            float2 v1 = make_float2(fmaxf(acc[nt][2] + ba, 0.0f),
                                    fmaxf(acc[nt][3] + bb, 0.0f));
            *(float2*)&sm[U_H1S + r * 68 + cb]       = v0;
            *(float2*)&sm[U_H1S + (r + 8) * 68 + cb] = v1;
        }
    }
    __syncthreads();

    // ---- layers 2+3 fused (tid < 128, one atom each) ----
    if (tid < BM) {
        float h1r[H1_];
        #pragma unroll
        for (int q = 0; q < 16; q++)
            *(float4*)&h1r[q * 4] = *(const float4*)&sm[U_H1S + tid * 68 + q * 4];

        unsigned long long accg[8];
        #pragma unroll
        for (int gp = 0; gp < 8; gp++)
            accg[gp] = *(const unsigned long long*)&sm[S_B2 + gp * 2];

        const ulonglong2* w2v = (const ulonglong2*)&sm[S_W2];
        #pragma unroll 8
        for (int k = 0; k < H1_; k++) {
            unsigned long long hkk = pack2(h1r[k], h1r[k]);
            #pragma unroll
            for (int gq = 0; gq < 4; gq++) {
                ulonglong2 w = w2v[k * 4 + gq];
                ffma2(accg[gq * 2],     hkk, w.x);
                ffma2(accg[gq * 2 + 1], hkk, w.y);
            }
        }

        float o = sm[S_MISC + 1];
        #pragma unroll
        for (int gp = 0; gp < 8; gp++) {
            float lo, hi; unpack2(accg[gp], lo, hi);
            o += fmaxf(lo, 0.0f) * sm[S_W3 + gp * 2]
               + fmaxf(hi, 0.0f) * sm[S_W3 + gp * 2 + 1];
        }
        int idx = s_idx[tid];
        if (idx >= 0)
            g_atom[idx] = (o + sm[S_MISC]) * mask[idx];
    }
}

// ===========================================================================
// K3: deterministic reduction — warp per molecule, fixed shuffle tree.
// ===========================================================================
__global__ void k_reduce(float* __restrict__ out) {
    int warp = threadIdx.x >> 5, lane = threadIdx.x & 31;
    int m = blockIdx.x * 8 + warp;
    const float* p = g_atom + m * A_;
    float s = p[lane] + p[lane + 32];
    #pragma unroll
    for (int o = 16; o > 0; o >>= 1) s += __shfl_xor_sync(0xffffffffu, s, o);
    if (lane == 0) out[m] = s;
}

// ===========================================================================
extern "C" void kernel_launch(void* const* d_in, const int* in_sizes, int n_in,
                              void* d_out, int out_size) {
    const float* x    = (const float*)d_in[0];
    const float* mask = (const float*)d_in[1];
    const float* W1   = (const float*)d_in[2];
    const float* b1   = (const float*)d_in[3];
    const float* W2   = (const float*)d_in[4];
    const float* b2   = (const float*)d_in[5];
    const float* W3   = (const float*)d_in[6];
    const float* b3   = (const float*)d_in[7];

    cudaFuncSetAttribute(k_mlp, cudaFuncAttributeMaxDynamicSharedMemorySize,
                         SMEM_BYTES);

    k_init<<<1, 32>>>(b1, W2, b2, W3, b3);
    k_binit<<<T_, 256>>>(W1);
    k_bucket<<<NATOM / 256, 256>>>(x);
    k_mlp<<<MLP_BLOCKS, 256, SMEM_BYTES>>>(x, mask, W1, b1, W2, b2, W3, b3);
    k_reduce<<<B_ / 8, 256>>>((float*)d_out);
}

// round 11
// speedup vs baseline: 1.3898x; 1.0625x over previous
#include <cuda_runtime.h>
#include <cstdint>

// ---------------------------------------------------------------------------
// MultiMolNet: per-atom typed 3-layer MLP + masked per-molecule sum.
// Identity: sum over all 8 type-MLPs = f_{type}(feats) + (C - Z_type),
// Z_t = f_t(0), C = sum_t Z_t  ->  one MLP eval per atom.
//
// R11: BM=256, 2 m-tiles/warp (halves B-fragment L1 traffic; R9 ncu showed
//      L1-bound 58.6% on B LDGs). A streamed via cp.async fragment scatter
//      in FOUR quarter-k chunks (4 ks = 32 k each), double-buffered 32 KB
//      buffers (R10 crashed: half-k buffers are 64 KB, overflowed smem).
//      Tail k>=124 handled by STS-zero in the unified issue loop.
// ---------------------------------------------------------------------------

namespace {
constexpr int B_  = 4096;
constexpr int A_  = 64;
constexpr int F_  = 124;
constexpr int T_  = 8;
constexpr int H1_ = 64;
constexpr int H2_ = 16;
constexpr int NATOM = B_ * A_;     // 262144
constexpr int ROW   = F_ + 1;      // 125
constexpr int BM    = 256;         // atoms per CTA (two 128-row MMA tiles)
constexpr int MLP_BLOCKS = NATOM / BM + T_;   // 1032
constexpr int NKS   = 16;          // k-steps of 8 (124 padded to 128)

// --- smem layout (float indices) ---
// ABUF[2]: quarter-k A fragments [4ks][16wb][32lane][float4]
//          = 4*16*32*4 = 8192 floats (32 KB) each.  (size derived from shape)
constexpr int ABUF_SZ = 4 * 16 * 32 * 4;      // 8192
constexpr int ABUF0 = 0;
constexpr int ABUF1 = ABUF_SZ;                // 8192
// h1s[256][68] overlays [0..17408) after layer-1 (barrier-protected).
constexpr int U_H1S = 0;
constexpr int S_W2   = 17408;       // 1024 (byte 69632, 16B aligned)
constexpr int S_B1   = S_W2 + 1024;
constexpr int S_B2   = S_B1 + 64;
constexpr int S_W3   = S_B2 + 16;
constexpr int S_MISC = S_W3 + 16;   // [0]=corr, [1]=b3
constexpr int S_IDX  = S_MISC + 4;  // 256 ints
constexpr int SMEM_FLOATS = S_IDX + BM;
constexpr int SMEM_BYTES  = SMEM_FLOATS * 4;   // 75152 B -> 2 CTAs/SM
static_assert(ABUF1 + ABUF_SZ <= S_W2, "A buffers must fit under params");
}

// ---- scratch ----
__device__ int    g_counts[T_];
__device__ int    g_bucket[T_ * NATOM];
__device__ float  g_corr[T_];
__device__ float  g_atom[NATOM];
// B fragments per type: [16ks][8nt][32lane] x (h0,h1,l0,l1)
__device__ float4 g_bfrag[T_ * NKS * 8 * 32];   // 512 KB

// ---- helpers ----
__device__ __forceinline__ uint32_t smem_u32(const void* p) {
    return (uint32_t)__cvta_generic_to_shared(p);
}
__device__ __forceinline__ float tf32_hi(float x) {
    uint32_t u;
    asm("cvt.rna.tf32.f32 %0, %1;" : "=r"(u) : "f"(x));
    return __uint_as_float(u);
}
__device__ __forceinline__ void cp_async4(uint32_t dst, const void* src) {
    asm volatile("cp.async.ca.shared.global [%0], [%1], 4;"
                 :: "r"(dst), "l"(src) : "memory");
}
#define CP_COMMIT() asm volatile("cp.async.commit_group;" ::: "memory")
#define CP_WAIT(n)  asm volatile("cp.async.wait_group %0;" :: "n"(n) : "memory")

// m16n8k8 tf32 MMA: D(f32) += A(tf32) * B(tf32). Row-major A, col-major B.
__device__ __forceinline__ void mma_tf32(float d[4], const uint32_t a[4],
                                         uint32_t b0, uint32_t b1) {
    asm volatile(
        "mma.sync.aligned.m16n8k8.row.col.f32.tf32.tf32.f32 "
        "{%0,%1,%2,%3}, {%4,%5,%6,%7}, {%8,%9}, {%0,%1,%2,%3};"
        : "+f"(d[0]), "+f"(d[1]), "+f"(d[2]), "+f"(d[3])
        : "r"(a[0]), "r"(a[1]), "r"(a[2]), "r"(a[3]), "r"(b0), "r"(b1));
}

// ---- f32x2 packed FMA (layer 2) ----
__device__ __forceinline__ void ffma2(unsigned long long& d,
                                      unsigned long long a, unsigned long long b) {
    asm("fma.rn.f32x2 %0, %1, %2, %3;" : "=l"(d) : "l"(a), "l"(b), "l"(d));
}
__device__ __forceinline__ unsigned long long pack2(float lo, float hi) {
    unsigned long long r;
    asm("mov.b64 %0, {%1, %2};" : "=l"(r) : "f"(lo), "f"(hi));
    return r;
}
__device__ __forceinline__ void unpack2(unsigned long long v, float& lo, float& hi) {
    asm("mov.b64 {%0, %1}, %2;" : "=f"(lo), "=f"(hi) : "l"(v));
}

// ===========================================================================
// K0: Z_t = f_t(0), corr_t = C - Z_t; zero counters.
// ===========================================================================
__global__ void k_init(const float* __restrict__ b1, const float* __restrict__ W2,
                       const float* __restrict__ b2, const float* __restrict__ W3,
                       const float* __restrict__ b3) {
    __shared__ float zs[T_];
    int t = threadIdx.x;
    if (t < T_) {
        g_counts[t] = 0;
        float h1z[H1_];
        #pragma unroll
        for (int h = 0; h < H1_; h++) h1z[h] = fmaxf(b1[t * H1_ + h], 0.0f);
        float o = b3[t];
        for (int g = 0; g < H2_; g++) {
            float s = b2[t * H2_ + g];
            #pragma unroll
            for (int k = 0; k < H1_; k++)
                s += h1z[k] * W2[t * H1_ * H2_ + k * H2_ + g];
            o += fmaxf(s, 0.0f) * W3[t * H2_ + g];
        }
        zs[t] = o;
    }
    __syncthreads();
    if (t < T_) {
        float C = 0.0f;
        #pragma unroll
        for (int tt = 0; tt < T_; tt++) C += zs[tt];
        g_corr[t] = C - zs[t];
    }
}

// ===========================================================================
// K0b: precompute B (W1) hi/lo fragments per type.
// frag map (m16n8k8 B, col-major): b0=(k=l&3, n=l>>2), b1=(k+4, n)
// ===========================================================================
__global__ void k_binit(const float* __restrict__ W1) {
    int t = blockIdx.x;
    const float* w = W1 + t * F_ * H1_;
    for (int s = threadIdx.x; s < NKS * 8 * 32; s += 256) {
        int l = s & 31, nt = (s >> 5) & 7, ks = s >> 8;
        int n  = nt * 8 + (l >> 2);
        int k0 = ks * 8 + (l & 3);
        float v0 = (k0 < F_)     ? w[k0 * H1_ + n]       : 0.0f;
        float v1 = (k0 + 4 < F_) ? w[(k0 + 4) * H1_ + n] : 0.0f;
        float h0 = tf32_hi(v0), h1 = tf32_hi(v1);
        g_bfrag[t * (NKS * 8 * 32) + s] = make_float4(h0, h1, v0 - h0, v1 - h1);
    }
}

// ===========================================================================
// K1: bucket atom indices by type (order nondeterminism harmless).
// ===========================================================================
__global__ void k_bucket(const float* __restrict__ x) {
    __shared__ int scnt[T_], sbase[T_];
    int tid = threadIdx.x;
    if (tid < T_) scnt[tid] = 0;
    __syncthreads();
    int i = blockIdx.x * 256 + tid;
    int t = (int)x[(long long)i * ROW];
    int r = atomicAdd(&scnt[t], 1);
    __syncthreads();
    if (tid < T_) sbase[tid] = atomicAdd(&g_counts[tid], scnt[tid]);
    __syncthreads();
    g_bucket[t * NATOM + sbase[t] + r] = i;
}

// ===========================================================================
// K2: layer-1 via mma.sync tf32; 256 atoms/CTA, warp w owns m-tiles
//     wb=w and wb=w+8. A streamed in 4 quarter-k chunks (double buffered).
// A frag map (m16n8k8): a0=(r=l>>2,k=l&3) a1=(r+8,k) a2=(r,k+4) a3=(r+8,k+4)
// ===========================================================================
__global__ void __launch_bounds__(256, 2)
k_mlp(const float* __restrict__ x,  const float* __restrict__ mask,
      const float* __restrict__ W1, const float* __restrict__ b1,
      const float* __restrict__ W2, const float* __restrict__ b2,
      const float* __restrict__ W3, const float* __restrict__ b3) {
    extern __shared__ float sm[];
    int* s_idx = (int*)&sm[S_IDX];
    const int tid  = threadIdx.x;
    const int warp = tid >> 5;
    const int lane = tid & 31;

    // ---- map block -> (type, tile) ----
    int t = -1, tile = 0, cnt = 0;
    {
        int rem = blockIdx.x;
        #pragma unroll
        for (int tt = 0; tt < T_; tt++) {
            int c  = g_counts[tt];
            int nt = (c + BM - 1) >> 8;
            if (t < 0) {
                if (rem < nt) { t = tt; tile = rem; cnt = c; }
                else rem -= nt;
            }
        }
    }
    if (t < 0) return;

    const uint32_t smb = smem_u32(sm);

    // ---- prologue: params, atom indices, zero both A buffers ----
    for (int i = tid; i < H1_ * H2_; i += 256)
        sm[S_W2 + i] = W2[t * H1_ * H2_ + i];
    if (tid < H1_) sm[S_B1 + tid] = b1[t * H1_ + tid];
    if (tid < H2_) sm[S_B2 + tid] = b2[t * H2_ + tid];
    if (tid < H2_) sm[S_W3 + tid] = W3[t * H2_ + tid];
    if (tid == 0) { sm[S_MISC] = g_corr[t]; sm[S_MISC + 1] = b3[t]; }
    {
        int gi = tile * BM + tid;
        s_idx[tid] = (gi < cnt) ? g_bucket[t * NATOM + gi] : -1;
    }
    {
        float4 z4 = make_float4(0.f, 0.f, 0.f, 0.f);
        #pragma unroll
        for (int q = 0; q < 2 * ABUF_SZ / 1024; q++)   // 16 stores: 16384 floats
            *(float4*)&sm[(tid + q * 256) * 4] = z4;
    }
    __syncthreads();   // zeros + s_idx visible before cp.async writes

    // ---- A gather: cp.async scatter into fragment order, one 32-k chunk ----
    // warp w fills atom slots [32w, 32w+32); lane = k within chunk.
    // Lanes with k >= F_ write a zero STS instead (buffer is free here),
    // which also cleans stale data when a buffer is reused for chunk 3.
    auto issue_chunk = [&](int c, int abuf) {
        const int slot0 = warp * 32;
        const int kbase = c * 32;
        const int k     = kbase + lane;
        const int ksl   = lane >> 3;          // local ks (0..3)
        const int kk    = lane & 7;
        #pragma unroll 4
        for (int a = 0; a < 32; a++) {
            int s   = slot0 + a;
            int sid = s_idx[s];
            if (sid < 0) continue;            // entries stay zero (never written)
            const int wb       = s >> 4;
            const int rr       = s & 15;
            const int reg      = ((rr >= 8) ? 1 : 0) + ((kk >= 4) ? 2 : 0);
            const int dl       = (rr & 7) * 4 + (kk & 3);
            uint32_t dst = smb + (uint32_t)(
                (abuf + ((ksl * 16 + wb) * 32 + dl) * 4 + reg) * 4);
            if (k < F_) {
                cp_async4(dst, x + (long long)sid * ROW + 1 + k);
            } else {
                uint32_t z = 0;
                asm volatile("st.shared.b32 [%0], %1;" :: "r"(dst), "r"(z));
            }
        }
    };

    // ---- one quarter-k chunk of MMAs: 4 ks x 8 nt x 2 m x 3 ----
    float acc[2][8][4];
    #pragma unroll
    for (int m = 0; m < 2; m++)
        #pragma unroll
        for (int nt = 0; nt < 8; nt++)
            #pragma unroll
            for (int j = 0; j < 4; j++) acc[m][nt][j] = 0.0f;

    const float4* __restrict__ bfr = g_bfrag + t * (NKS * 8 * 32);
    auto compute_chunk = [&](int c, int abuf) {
        #pragma unroll
        for (int ksl = 0; ksl < 4; ksl++) {
            const int ks = c * 4 + ksl;
            uint32_t Ahi[2][4], Alo[2][4];
            #pragma unroll
            for (int m = 0; m < 2; m++) {
                const int wb = warp + m * 8;
                float4 av = *(const float4*)
                    &sm[abuf + ((ksl * 16 + wb) * 32 + lane) * 4];
                float a[4] = {av.x, av.y, av.z, av.w};
                #pragma unroll
                for (int j = 0; j < 4; j++) {
                    float hv = tf32_hi(a[j]);
                    Ahi[m][j] = __float_as_uint(hv);
                    Alo[m][j] = __float_as_uint(a[j] - hv);
                }
            }
            #pragma unroll
            for (int nt = 0; nt < 8; nt++) {
                float4 bv = __ldg(&bfr[(ks * 8 + nt) * 32 + lane]);
                uint32_t bh0 = __float_as_uint(bv.x), bh1 = __float_as_uint(bv.y);
                uint32_t bl0 = __float_as_uint(bv.z), bl1 = __float_as_uint(bv.w);
                #pragma unroll
                for (int m = 0; m < 2; m++) {
                    mma_tf32(acc[m][nt], Ahi[m], bh0, bh1);   // Ah*Bh
                    mma_tf32(acc[m][nt], Ahi[m], bl0, bl1);   // Ah*Bl
                    mma_tf32(acc[m][nt], Alo[m], bh0, bh1);   // Al*Bh
                }
            }
        }
    };

    // ---- double-buffered pipeline over 4 chunks ----
    issue_chunk(0, ABUF0); CP_COMMIT();
    issue_chunk(1, ABUF1); CP_COMMIT();
    CP_WAIT(1); __syncthreads();          // chunk0 resident (all warps)
    compute_chunk(0, ABUF0);
    __syncthreads();                      // ABUF0 free
    issue_chunk(2, ABUF0); CP_COMMIT();
    CP_WAIT(1); __syncthreads();          // chunk1 resident
    compute_chunk(1, ABUF1);
    __syncthreads();                      // ABUF1 free
    issue_chunk(3, ABUF1); CP_COMMIT();
    CP_WAIT(1); __syncthreads();          // chunk2 resident
    compute_chunk(2, ABUF0);
    CP_WAIT(0); __syncthreads();          // chunk3 resident
    compute_chunk(3, ABUF1);
    __syncthreads();                      // all ABUF reads done (h1s overlay)

    // ---- layer-1 epilogue: bias + relu -> h1s[atom][68] ----
    // D frag: c0=(r=l>>2, col=2*(l&3)) c1=(r,col+1) c2=(r+8,col) c3=(r+8,col+1)
    {
        #pragma unroll
        for (int m = 0; m < 2; m++) {
            const int r = (warp + m * 8) * 16 + (lane >> 2);
            #pragma unroll
            for (int nt = 0; nt < 8; nt++) {
                int cb = nt * 8 + 2 * (lane & 3);
                float ba = sm[S_B1 + cb], bb = sm[S_B1 + cb + 1];
                float2 v0 = make_float2(fmaxf(acc[m][nt][0] + ba, 0.0f),
                                        fmaxf(acc[m][nt][1] + bb, 0.0f));
                float2 v1 = make_float2(fmaxf(acc[m][nt][2] + ba, 0.0f),
                                        fmaxf(acc[m][nt][3] + bb, 0.0f));
                *(float2*)&sm[U_H1S + r * 68 + cb]       = v0;
                *(float2*)&sm[U_H1S + (r + 8) * 68 + cb] = v1;
            }
        }
    }
    __syncthreads();

    // ---- layers 2+3 fused: all 256 threads, one atom slot each ----
    {
        float h1r[H1_];
        #pragma unroll
        for (int q = 0; q < 16; q++)
            *(float4*)&h1r[q * 4] = *(const float4*)&sm[U_H1S + tid * 68 + q * 4];

        unsigned long long accg[8];
        #pragma unroll
        for (int gp = 0; gp < 8; gp++)
            accg[gp] = *(const unsigned long long*)&sm[S_B2 + gp * 2];

        const ulonglong2* w2v = (const ulonglong2*)&sm[S_W2];
        #pragma unroll 8
        for (int k = 0; k < H1_; k++) {
            unsigned long long hkk = pack2(h1r[k], h1r[k]);
            #pragma unroll
            for (int gq = 0; gq < 4; gq++) {
                ulonglong2 w = w2v[k * 4 + gq];
                ffma2(accg[gq * 2],     hkk, w.x);
                ffma2(accg[gq * 2 + 1], hkk, w.y);
            }
        }

        float o = sm[S_MISC + 1];
        #pragma unroll
        for (int gp = 0; gp < 8; gp++) {
            float lo, hi; unpack2(accg[gp], lo, hi);
            o += fmaxf(lo, 0.0f) * sm[S_W3 + gp * 2]
               + fmaxf(hi, 0.0f) * sm[S_W3 + gp * 2 + 1];
        }
        int idx = s_idx[tid];
        if (idx >= 0)
            g_atom[idx] = (o + sm[S_MISC]) * mask[idx];
    }
}

// ===========================================================================
// K3: deterministic reduction — warp per molecule, fixed shuffle tree.
// ===========================================================================
__global__ void k_reduce(float* __restrict__ out) {
    int warp = threadIdx.x >> 5, lane = threadIdx.x & 31;
    int m = blockIdx.x * 8 + warp;
    const float* p = g_atom + m * A_;
    float s = p[lane] + p[lane + 32];
    #pragma unroll
    for (int o = 16; o > 0; o >>= 1) s += __shfl_xor_sync(0xffffffffu, s, o);
    if (lane == 0) out[m] = s;
}

// ===========================================================================
extern "C" void kernel_launch(void* const* d_in, const int* in_sizes, int n_in,
                              void* d_out, int out_size) {
    const float* x    = (const float*)d_in[0];
    const float* mask = (const float*)d_in[1];
    const float* W1   = (const float*)d_in[2];
    const float* b1   = (const float*)d_in[3];
    const float* W2   = (const float*)d_in[4];
    const float* b2   = (const float*)d_in[5];
    const float* W3   = (const float*)d_in[6];
    const float* b3   = (const float*)d_in[7];

    cudaFuncSetAttribute(k_mlp, cudaFuncAttributeMaxDynamicSharedMemorySize,
                         SMEM_BYTES);

    k_init<<<1, 32>>>(b1, W2, b2, W3, b3);
    k_binit<<<T_, 256>>>(W1);
    k_bucket<<<NATOM / 256, 256>>>(x);
    k_mlp<<<MLP_BLOCKS, 256, SMEM_BYTES>>>(x, mask, W1, b1, W2, b2, W3, b3);
    k_reduce<<<B_ / 8, 256>>>((float*)d_out);
}

// round 12
// speedup vs baseline: 1.5762x; 1.1342x over previous
#include <cuda_runtime.h>
#include <cstdint>

// ---------------------------------------------------------------------------
// MultiMolNet: per-atom typed 3-layer MLP + masked per-molecule sum.
// Identity: sum over all 8 type-MLPs = f_{type}(feats) + (C - Z_type),
// Z_t = f_t(0), C = sum_t Z_t  ->  one MLP eval per atom.
//
// R12: contiguous cp.async A staging (R11 ncu: L1 62% — the fragment
//      scatter cost ~5K wavefronts/CTA). A rows stored [atom][36] (padded:
//      bank-conflict-free fragment reads via 4x LDS.32); fragment reorder
//      folded into mainloop load addresses. BM=256, 2 m-tiles/warp,
//      B fragments precomputed per type in gmem. k_binit widened to 64 blocks.
// ---------------------------------------------------------------------------

namespace {
constexpr int B_  = 4096;
constexpr int A_  = 64;
constexpr int F_  = 124;
constexpr int T_  = 8;
constexpr int H1_ = 64;
constexpr int H2_ = 16;
constexpr int NATOM = B_ * A_;     // 262144
constexpr int ROW   = F_ + 1;      // 125
constexpr int BM    = 256;         // atoms per CTA (two 128-row MMA tiles)
constexpr int MLP_BLOCKS = NATOM / BM + T_;   // 1032
constexpr int NKS   = 16;          // k-steps of 8 (124 padded to 128)

// --- smem layout (float indices) ---
// ASTG[2]: contiguous A chunk [256 atoms][36 floats] (32 k + 4 pad) = 9216 fl.
constexpr int ASTG_ROW = 36;
constexpr int ASTG_SZ  = BM * ASTG_ROW;       // 9216
constexpr int ASTG0 = 0;
constexpr int ASTG1 = ASTG_SZ;                // 9216; region ends 18432
// h1s[256][68] overlays [0..17408) after layer-1 (barrier-protected).
constexpr int U_H1S = 0;
constexpr int S_W2   = 2 * ASTG_SZ;           // 18432 (byte 73728, 16B aligned)
constexpr int S_B1   = S_W2 + 1024;
constexpr int S_B2   = S_B1 + 64;
constexpr int S_W3   = S_B2 + 16;
constexpr int S_MISC = S_W3 + 16;   // [0]=corr, [1]=b3
constexpr int S_IDX  = S_MISC + 4;  // 256 ints
constexpr int SMEM_FLOATS = S_IDX + BM;
constexpr int SMEM_BYTES  = SMEM_FLOATS * 4;   // 79248 B -> 2 CTAs/SM
}

// ---- scratch ----
__device__ int    g_counts[T_];
__device__ int    g_bucket[T_ * NATOM];
__device__ float  g_corr[T_];
__device__ float  g_atom[NATOM];
// B fragments per type: [16ks][8nt][32lane] x (h0,h1,l0,l1)
__device__ float4 g_bfrag[T_ * NKS * 8 * 32];   // 512 KB

// ---- helpers ----
__device__ __forceinline__ uint32_t smem_u32(const void* p) {
    return (uint32_t)__cvta_generic_to_shared(p);
}
__device__ __forceinline__ float tf32_hi(float x) {
    uint32_t u;
    asm("cvt.rna.tf32.f32 %0, %1;" : "=r"(u) : "f"(x));
    return __uint_as_float(u);
}
__device__ __forceinline__ void cp_async4(uint32_t dst, const void* src) {
    asm volatile("cp.async.ca.shared.global [%0], [%1], 4;"
                 :: "r"(dst), "l"(src) : "memory");
}
__device__ __forceinline__ void sts_zero(uint32_t dst) {
    asm volatile("st.shared.b32 [%0], %1;" :: "r"(dst), "r"(0u));
}
#define CP_COMMIT() asm volatile("cp.async.commit_group;" ::: "memory")
#define CP_WAIT(n)  asm volatile("cp.async.wait_group %0;" :: "n"(n) : "memory")

// m16n8k8 tf32 MMA: D(f32) += A(tf32) * B(tf32). Row-major A, col-major B.
__device__ __forceinline__ void mma_tf32(float d[4], const uint32_t a[4],
                                         uint32_t b0, uint32_t b1) {
    asm volatile(
        "mma.sync.aligned.m16n8k8.row.col.f32.tf32.tf32.f32 "
        "{%0,%1,%2,%3}, {%4,%5,%6,%7}, {%8,%9}, {%0,%1,%2,%3};"
        : "+f"(d[0]), "+f"(d[1]), "+f"(d[2]), "+f"(d[3])
        : "r"(a[0]), "r"(a[1]), "r"(a[2]), "r"(a[3]), "r"(b0), "r"(b1));
}

// ---- f32x2 packed FMA (layer 2) ----
__device__ __forceinline__ void ffma2(unsigned long long& d,
                                      unsigned long long a, unsigned long long b) {
    asm("fma.rn.f32x2 %0, %1, %2, %3;" : "=l"(d) : "l"(a), "l"(b), "l"(d));
}
__device__ __forceinline__ unsigned long long pack2(float lo, float hi) {
    unsigned long long r;
    asm("mov.b64 %0, {%1, %2};" : "=l"(r) : "f"(lo), "f"(hi));
    return r;
}
__device__ __forceinline__ void unpack2(unsigned long long v, float& lo, float& hi) {
    asm("mov.b64 {%0, %1}, %2;" : "=f"(lo), "=f"(hi) : "l"(v));
}

// ===========================================================================
// K0: Z_t = f_t(0), corr_t = C - Z_t; zero counters.
// ===========================================================================
__global__ void k_init(const float* __restrict__ b1, const float* __restrict__ W2,
                       const float* __restrict__ b2, const float* __restrict__ W3,
                       const float* __restrict__ b3) {
    __shared__ float zs[T_];
    int t = threadIdx.x;
    if (t < T_) {
        g_counts[t] = 0;
        float h1z[H1_];
        #pragma unroll
        for (int h = 0; h < H1_; h++) h1z[h] = fmaxf(b1[t * H1_ + h], 0.0f);
        float o = b3[t];
        for (int g = 0; g < H2_; g++) {
            float s = b2[t * H2_ + g];
            #pragma unroll
            for (int k = 0; k < H1_; k++)
                s += h1z[k] * W2[t * H1_ * H2_ + k * H2_ + g];
            o += fmaxf(s, 0.0f) * W3[t * H2_ + g];
        }
        zs[t] = o;
    }
    __syncthreads();
    if (t < T_) {
        float C = 0.0f;
        #pragma unroll
        for (int tt = 0; tt < T_; tt++) C += zs[tt];
        g_corr[t] = C - zs[t];
    }
}

// ===========================================================================
// K0b: precompute B (W1) hi/lo fragments per type. 64 blocks.
// frag map (m16n8k8 B, col-major): b0=(k=l&3, n=l>>2), b1=(k+4, n)
// ===========================================================================
__global__ void k_binit(const float* __restrict__ W1) {
    int t    = blockIdx.x >> 3;
    int part = blockIdx.x & 7;
    const float* w = W1 + t * F_ * H1_;
    int s = part * 512 + threadIdx.x;         // 512 = 4096/8, blockDim 512
    {
        int l = s & 31, nt = (s >> 5) & 7, ks = s >> 8;
        int n  = nt * 8 + (l >> 2);
        int k0 = ks * 8 + (l & 3);
        float v0 = (k0 < F_)     ? w[k0 * H1_ + n]       : 0.0f;
        float v1 = (k0 + 4 < F_) ? w[(k0 + 4) * H1_ + n] : 0.0f;
        float h0 = tf32_hi(v0), h1 = tf32_hi(v1);
        g_bfrag[t * (NKS * 8 * 32) + s] = make_float4(h0, h1, v0 - h0, v1 - h1);
    }
}

// ===========================================================================
// K1: bucket atom indices by type (order nondeterminism harmless).
// ===========================================================================
__global__ void k_bucket(const float* __restrict__ x) {
    __shared__ int scnt[T_], sbase[T_];
    int tid = threadIdx.x;
    if (tid < T_) scnt[tid] = 0;
    __syncthreads();
    int i = blockIdx.x * 256 + tid;
    int t = (int)x[(long long)i * ROW];
    int r = atomicAdd(&scnt[t], 1);
    __syncthreads();
    if (tid < T_) sbase[tid] = atomicAdd(&g_counts[tid], scnt[tid]);
    __syncthreads();
    g_bucket[t * NATOM + sbase[t] + r] = i;
}

// ===========================================================================
// K2: layer-1 via mma.sync tf32; 256 atoms/CTA, warp w owns m-tiles
//     wb=w and wb=w+8. A staged contiguously in 4 quarter-k chunks
//     (double buffered); fragment reorder folded into LDS addresses.
// A frag map (m16n8k8): a0=(r=l>>2,k=l&3) a1=(r+8,k) a2=(r,k+4) a3=(r+8,k+4)
// ===========================================================================
__global__ void __launch_bounds__(256, 2)
k_mlp(const float* __restrict__ x,  const float* __restrict__ mask,
      const float* __restrict__ W1, const float* __restrict__ b1,
      const float* __restrict__ W2, const float* __restrict__ b2,
      const float* __restrict__ W3, const float* __restrict__ b3) {
    extern __shared__ float sm[];
    int* s_idx = (int*)&sm[S_IDX];
    const int tid  = threadIdx.x;
    const int warp = tid >> 5;
    const int lane = tid & 31;

    // ---- map block -> (type, tile) ----
    int t = -1, tile = 0, cnt = 0;
    {
        int rem = blockIdx.x;
        #pragma unroll
        for (int tt = 0; tt < T_; tt++) {
            int c  = g_counts[tt];
            int nt = (c + BM - 1) >> 8;
            if (t < 0) {
                if (rem < nt) { t = tt; tile = rem; cnt = c; }
                else rem -= nt;
            }
        }
    }
    if (t < 0) return;

    const uint32_t smb = smem_u32(sm);

    // ---- prologue: params + atom indices ----
    for (int i = tid; i < H1_ * H2_; i += 256)
        sm[S_W2 + i] = W2[t * H1_ * H2_ + i];
    if (tid < H1_) sm[S_B1 + tid] = b1[t * H1_ + tid];
    if (tid < H2_) sm[S_B2 + tid] = b2[t * H2_ + tid];
    if (tid < H2_) sm[S_W3 + tid] = W3[t * H2_ + tid];
    if (tid == 0) { sm[S_MISC] = g_corr[t]; sm[S_MISC + 1] = b3[t]; }
    {
        int gi = tile * BM + tid;
        s_idx[tid] = (gi < cnt) ? g_bucket[t * NATOM + gi] : -1;
    }
    __syncthreads();   // s_idx visible before cp.async issue

    // ---- A staging: contiguous rows, lane = k within chunk ----
    // warp w fills atom slots [32w, 32w+32); tail k / invalid slots zeroed.
    auto issue_chunk = [&](int c, int astg) {
        const int slot0   = warp * 32;
        const int k       = c * 32 + lane;
        const bool k_ok   = (k < F_);
        uint32_t dst = smb + (uint32_t)((astg + slot0 * ASTG_ROW + lane) * 4);
        #pragma unroll 8
        for (int a = 0; a < 32; a++) {
            int sid = s_idx[slot0 + a];
            if (sid >= 0 && k_ok)
                cp_async4(dst, x + (long long)sid * ROW + 1 + k);
            else
                sts_zero(dst);
            dst += ASTG_ROW * 4;
        }
    };

    // ---- accumulators ----
    float acc[2][8][4];
    #pragma unroll
    for (int m = 0; m < 2; m++)
        #pragma unroll
        for (int nt = 0; nt < 8; nt++)
            #pragma unroll
            for (int j = 0; j < 4; j++) acc[m][nt][j] = 0.0f;

    const float4* __restrict__ bfr = g_bfrag + t * (NKS * 8 * 32);

    // ---- one quarter-k chunk: 4 ks x (2m frag-load) x 8 nt x 6 MMA ----
    // a0 addr: (wb*16 + (l>>2))*36 + ksl*8 + (l&3); bank = 4*(l>>2)+(l&3)+8ksl
    //   -> 32 distinct banks, conflict-free scalar LDS.
    auto compute_chunk = [&](int c, int astg) {
        const int rbase = astg + (warp * 16 + (lane >> 2)) * ASTG_ROW + (lane & 3);
        #pragma unroll
        for (int ksl = 0; ksl < 4; ksl++) {
            const int ks = c * 4 + ksl;
            uint32_t Ahi[2][4], Alo[2][4];
            #pragma unroll
            for (int m = 0; m < 2; m++) {
                const int b0 = rbase + m * (128 * ASTG_ROW) + ksl * 8;
                float a0 = sm[b0];
                float a1 = sm[b0 + 8 * ASTG_ROW];
                float a2 = sm[b0 + 4];
                float a3 = sm[b0 + 8 * ASTG_ROW + 4];
                float h;
                h = tf32_hi(a0); Ahi[m][0] = __float_as_uint(h);
                Alo[m][0] = __float_as_uint(a0 - h);
                h = tf32_hi(a1); Ahi[m][1] = __float_as_uint(h);
                Alo[m][1] = __float_as_uint(a1 - h);
                h = tf32_hi(a2); Ahi[m][2] = __float_as_uint(h);
                Alo[m][2] = __float_as_uint(a2 - h);
                h = tf32_hi(a3); Ahi[m][3] = __float_as_uint(h);
                Alo[m][3] = __float_as_uint(a3 - h);
            }
            #pragma unroll
            for (int nt = 0; nt < 8; nt++) {
                float4 bv = __ldg(&bfr[(ks * 8 + nt) * 32 + lane]);
                uint32_t bh0 = __float_as_uint(bv.x), bh1 = __float_as_uint(bv.y);
                uint32_t bl0 = __float_as_uint(bv.z), bl1 = __float_as_uint(bv.w);
                #pragma unroll
                for (int m = 0; m < 2; m++) {
                    mma_tf32(acc[m][nt], Ahi[m], bh0, bh1);   // Ah*Bh
                    mma_tf32(acc[m][nt], Ahi[m], bl0, bl1);   // Ah*Bl
                    mma_tf32(acc[m][nt], Alo[m], bh0, bh1);   // Al*Bh
                }
            }
        }
    };

    // ---- double-buffered pipeline over 4 chunks ----
    issue_chunk(0, ASTG0); CP_COMMIT();
    issue_chunk(1, ASTG1); CP_COMMIT();
    CP_WAIT(1); __syncthreads();          // chunk0 resident (all warps)
    compute_chunk(0, ASTG0);
    __syncthreads();                      // ASTG0 free
    issue_chunk(2, ASTG0); CP_COMMIT();
    CP_WAIT(1); __syncthreads();          // chunk1 resident
    compute_chunk(1, ASTG1);
    __syncthreads();                      // ASTG1 free
    issue_chunk(3, ASTG1); CP_COMMIT();
    CP_WAIT(1); __syncthreads();          // chunk2 resident
    compute_chunk(2, ASTG0);
    CP_WAIT(0); __syncthreads();          // chunk3 resident
    compute_chunk(3, ASTG1);
    __syncthreads();                      // all ASTG reads done (h1s overlay)

    // ---- layer-1 epilogue: bias + relu -> h1s[atom][68] ----
    // D frag: c0=(r=l>>2, col=2*(l&3)) c1=(r,col+1) c2=(r+8,col) c3=(r+8,col+1)
    {
        #pragma unroll
        for (int m = 0; m < 2; m++) {
            const int r = (warp + m * 8) * 16 + (lane >> 2);
            #pragma unroll
            for (int nt = 0; nt < 8; nt++) {
                int cb = nt * 8 + 2 * (lane & 3);
                float ba = sm[S_B1 + cb], bb = sm[S_B1 + cb + 1];
                float2 v0 = make_float2(fmaxf(acc[m][nt][0] + ba, 0.0f),
                                        fmaxf(acc[m][nt][1] + bb, 0.0f));
                float2 v1 = make_float2(fmaxf(acc[m][nt][2] + ba, 0.0f),
                                        fmaxf(acc[m][nt][3] + bb, 0.0f));
                *(float2*)&sm[U_H1S + r * 68 + cb]       = v0;
                *(float2*)&sm[U_H1S + (r + 8) * 68 + cb] = v1;
            }
        }
    }
    __syncthreads();

    // ---- layers 2+3 fused: all 256 threads, one atom slot each ----
    {
        float h1r[H1_];
        #pragma unroll
        for (int q = 0; q < 16; q++)
            *(float4*)&h1r[q * 4] = *(const float4*)&sm[U_H1S + tid * 68 + q * 4];

        unsigned long long accg[8];
        #pragma unroll
        for (int gp = 0; gp < 8; gp++)
            accg[gp] = *(const unsigned long long*)&sm[S_B2 + gp * 2];

        const ulonglong2* w2v = (const ulonglong2*)&sm[S_W2];
        #pragma unroll 8
        for (int k = 0; k < H1_; k++) {
            unsigned long long hkk = pack2(h1r[k], h1r[k]);
            #pragma unroll
            for (int gq = 0; gq < 4; gq++) {
                ulonglong2 w = w2v[k * 4 + gq];
                ffma2(accg[gq * 2],     hkk, w.x);
                ffma2(accg[gq * 2 + 1], hkk, w.y);
            }
        }

        float o = sm[S_MISC + 1];
        #pragma unroll
        for (int gp = 0; gp < 8; gp++) {
            float lo, hi; unpack2(accg[gp], lo, hi);
            o += fmaxf(lo, 0.0f) * sm[S_W3 + gp * 2]
               + fmaxf(hi, 0.0f) * sm[S_W3 + gp * 2 + 1];
        }
        int idx = s_idx[tid];
        if (idx >= 0)
            g_atom[idx] = (o + sm[S_MISC]) * mask[idx];
    }
}

// ===========================================================================
// K3: deterministic reduction — warp per molecule, fixed shuffle tree.
// ===========================================================================
__global__ void k_reduce(float* __restrict__ out) {
    int warp = threadIdx.x >> 5, lane = threadIdx.x & 31;
    int m = blockIdx.x * 8 + warp;
    const float* p = g_atom + m * A_;
    float s = p[lane] + p[lane + 32];
    #pragma unroll
    for (int o = 16; o > 0; o >>= 1) s += __shfl_xor_sync(0xffffffffu, s, o);
    if (lane == 0) out[m] = s;
}

// ===========================================================================
extern "C" void kernel_launch(void* const* d_in, const int* in_sizes, int n_in,
                              void* d_out, int out_size) {
    const float* x    = (const float*)d_in[0];
    const float* mask = (const float*)d_in[1];
    const float* W1   = (const float*)d_in[2];
    const float* b1   = (const float*)d_in[3];
    const float* W2   = (const float*)d_in[4];
    const float* b2   = (const float*)d_in[5];
    const float* W3   = (const float*)d_in[6];
    const float* b3   = (const float*)d_in[7];

    cudaFuncSetAttribute(k_mlp, cudaFuncAttributeMaxDynamicSharedMemorySize,
                         SMEM_BYTES);

    k_init<<<1, 32>>>(b1, W2, b2, W3, b3);
    k_binit<<<T_ * 8, 512>>>(W1);
    k_bucket<<<NATOM / 256, 256>>>(x);
    k_mlp<<<MLP_BLOCKS, 256, SMEM_BYTES>>>(x, mask, W1, b1, W2, b2, W3, b3);
    k_reduce<<<B_ / 8, 256>>>((float*)d_out);
}